// round 16
// baseline (speedup 1.0000x reference)
#include <cuda_runtime.h>
#include <cuda_fp16.h>
#include <cstdint>

// ---------------------------------------------------------------------------
// Problem constants
// ---------------------------------------------------------------------------
#define B_   2
#define S_   2048
#define DM_  768
#define NQK_ 16
#define DQK_ 16
#define NOV_ 256
#define VKV_ 16
#define SK_  (S_ + VKV_)     // 2064 keys = 16 + 16*128 (exact)
#define BS_  (B_ * S_)       // 4096 rows

// ---------------------------------------------------------------------------
// Device scratch
// ---------------------------------------------------------------------------
__device__ __half g_Ah  [BS_ * DM_];
__device__ __half g_Wh1 [DM_ * DM_];
__device__ __half g_Wh2 [DM_ * NOV_];
__device__ float  g_rot [S_ * 16];                  // [s][0..7]=sin, [8..15]=cos
__device__ __half g_Qh  [B_ * NQK_ * S_  * DQK_];
__device__ __half g_Kh  [B_ * NQK_ * SK_ * DQK_];
__device__ __half g_Vh  [B_ * NQK_ * SK_ * DQK_];
__device__ __half g_Zh  [BS_ * NOV_];

// ---------------------------------------------------------------------------
// helpers
// ---------------------------------------------------------------------------
__device__ __forceinline__ void grid_dep_sync() {
#if __CUDA_ARCH__ >= 900
    cudaGridDependencySynchronize();
#endif
}
__device__ __forceinline__ void trigger_dep_launch() {
#if __CUDA_ARCH__ >= 900
    cudaTriggerProgrammaticLaunchCompletion();
#endif
}
__device__ __forceinline__ uint32_t smem_u32(const void* p) {
    return (uint32_t)__cvta_generic_to_shared(p);
}
__device__ __forceinline__ void cp16(uint32_t s, const void* g) {
    asm volatile("cp.async.cg.shared.global [%0], [%1], 16;" :: "r"(s), "l"(g));
}
__device__ __forceinline__ float ex2f(float x) {
    float y; asm("ex2.approx.ftz.f32 %0, %1;" : "=f"(y) : "f"(x)); return y;
}
__device__ __forceinline__ uint32_t ex2h2(float lo, float hi) {
    uint32_t h, r;
    asm("cvt.rn.f16x2.f32 %0, %1, %2;" : "=r"(h) : "f"(hi), "f"(lo));
    asm("ex2.approx.f16x2 %0, %1;" : "=r"(r) : "r"(h));
    return r;
}
__device__ __forceinline__ void ldm4(uint32_t& r0, uint32_t& r1, uint32_t& r2, uint32_t& r3, uint32_t addr) {
    asm volatile("ldmatrix.sync.aligned.m8n8.x4.shared.b16 {%0,%1,%2,%3}, [%4];"
                 : "=r"(r0), "=r"(r1), "=r"(r2), "=r"(r3) : "r"(addr));
}
__device__ __forceinline__ void ldm4t(uint32_t& r0, uint32_t& r1, uint32_t& r2, uint32_t& r3, uint32_t addr) {
    asm volatile("ldmatrix.sync.aligned.m8n8.x4.trans.shared.b16 {%0,%1,%2,%3}, [%4];"
                 : "=r"(r0), "=r"(r1), "=r"(r2), "=r"(r3) : "r"(addr));
}
__device__ __forceinline__ void mma16816(float* d, const uint32_t* a, const uint32_t* b) {
    asm volatile("mma.sync.aligned.m16n8k16.row.col.f32.f16.f16.f32 "
                 "{%0,%1,%2,%3},{%4,%5,%6,%7},{%8,%9},{%0,%1,%2,%3};"
                 : "+f"(d[0]), "+f"(d[1]), "+f"(d[2]), "+f"(d[3])
                 : "r"(a[0]), "r"(a[1]), "r"(a[2]), "r"(a[3]), "r"(b[0]), "r"(b[1]));
}
__device__ __forceinline__ uint32_t packh2(float x, float y) {
    __half2 h = __floats2half2_rn(x, y);
    return *(uint32_t*)&h;
}

#define QSCALE 0.36067376022224085f   // 0.25 * log2(e)

// ---------------------------------------------------------------------------
// 1a) prep_core: Wh1 pack + resid->half (GEMM1 mainloop inputs)
//     blocks: [0,384) WQ/WK transpose | [384,1152) WV | [1152,2688) resid x8
// ---------------------------------------------------------------------------
#define PC_V0   384
#define PC_CV0  1152
#define PC_BLKS 2688

__global__ void prep_core(const float* __restrict__ WQ,
                          const float* __restrict__ WK,
                          const float* __restrict__ WV,
                          const float* __restrict__ resid)
{
    trigger_dep_launch();   // allow prep_rest to launch immediately
    __shared__ float sm[64 * 17];
    const int blk = blockIdx.x;
    const int t = threadIdx.x;

    if (blk < PC_V0) {
        int rem = blk, mat = rem / 192; rem %= 192;
        int h = rem / 12, d0 = (rem % 12) * 64;
        const float* W = mat ? WK : WQ;
        {
            int row = t >> 2, part = t & 3;
            float4 v = *(const float4*)&W[((size_t)h * DM_ + d0 + row) * DQK_ + part * 4];
            sm[row * 17 + part * 4 + 0] = v.x;
            sm[row * 17 + part * 4 + 1] = v.y;
            sm[row * 17 + part * 4 + 2] = v.z;
            sm[row * 17 + part * 4 + 3] = v.w;
        }
        __syncthreads();
        {
            int e = t >> 4, dcol = (t & 15) * 4;
            int c = mat * 256 + h * 16 + e;
            __half* dst = &g_Wh1[(size_t)c * DM_ + d0 + dcol];
            *(__half2*)&dst[0] = __floats2half2_rn(sm[(dcol + 0) * 17 + e], sm[(dcol + 1) * 17 + e]);
            *(__half2*)&dst[2] = __floats2half2_rn(sm[(dcol + 2) * 17 + e], sm[(dcol + 3) * 17 + e]);
        }
    } else if (blk < PC_CV0) {
        int idx = (blk - PC_V0) * 256 + t;
        g_Wh1[512 * DM_ + idx] = __float2half(WV[idx]);
    } else {
        int i = ((blk - PC_CV0) * 256 + t) * 8;       // 8 floats per thread
        float4 v0 = *(const float4*)(resid + i);
        float4 v1 = *(const float4*)(resid + i + 4);
        *(__half2*)&g_Ah[i]     = __floats2half2_rn(v0.x, v0.y);
        *(__half2*)&g_Ah[i + 2] = __floats2half2_rn(v0.z, v0.w);
        *(__half2*)&g_Ah[i + 4] = __floats2half2_rn(v1.x, v1.y);
        *(__half2*)&g_Ah[i + 6] = __floats2half2_rn(v1.z, v1.w);
    }
}

// ---------------------------------------------------------------------------
// 1b) prep_rest: Wh2 pack + rotary table + virtual KV (independent of core)
//     blocks: [0,192) W2 | [192,256) rot | [256,288) vkv
//     NOTE: never calls grid_dep_sync -> runs concurrent with prep_core.
// ---------------------------------------------------------------------------
#define PR_RT0  192
#define PR_VV0  256
#define PR_BLKS 288

__global__ void prep_rest(const float* __restrict__ WO,
                          const float* __restrict__ vk,
                          const float* __restrict__ vv)
{
    __shared__ float sm[64 * 17];
    const int blk = blockIdx.x;
    const int t = threadIdx.x;

    if (blk < PR_RT0) {
        int n0 = (blk / 12) * 16, m0 = (blk % 12) * 64;
        {
            int row = t >> 4, part = t & 15;
            float4 v = *(const float4*)&WO[(size_t)(n0 + row) * DM_ + m0 + part * 4];
            // reuse sm with stride 65 pattern packed into 64*17 buffer:
            // rows 0..15, 64 cols -> fits 16*65=1040 <= 1088
            sm[row * 65 + part * 4 + 0] = v.x;
            sm[row * 65 + part * 4 + 1] = v.y;
            sm[row * 65 + part * 4 + 2] = v.z;
            sm[row * 65 + part * 4 + 3] = v.w;
        }
        __syncthreads();
        {
            int mm = t >> 2, nn = (t & 3) * 4;
            __half* dst = &g_Wh2[(size_t)(m0 + mm) * NOV_ + n0 + nn];
            *(__half2*)&dst[0] = __floats2half2_rn(sm[(nn + 0) * 65 + mm], sm[(nn + 1) * 65 + mm]);
            *(__half2*)&dst[2] = __floats2half2_rn(sm[(nn + 2) * 65 + mm], sm[(nn + 3) * 65 + mm]);
        }
    } else if (blk < PR_VV0) {
        int idx = (blk - PR_RT0) * 256 + t;
        int s = idx >> 3, i = idx & 7;
        float freq = powf(10000.f, (float)i / 8.f);
        float sn, cs;
        sincosf((float)s / freq, &sn, &cs);
        g_rot[s * 16 + i]     = sn;
        g_rot[s * 16 + 8 + i] = cs;
    } else {
        int idx = (blk - PR_VV0) * 256 + t;
        int c = idx & 255;
        int m = (idx >> 8) & 15;
        int b = idx >> 12;
        int h = c >> 4, e = c & 15;
        size_t row = ((size_t)(b * NQK_ + h) * SK_ + S_ + m) * DQK_ + e;
        g_Kh[row] = __float2half(vk[m * 256 + c]);
        g_Vh[row] = __float2half(vv[m * 256 + c]);
    }
}

// ---------------------------------------------------------------------------
// 2) fp16 tensor-core GEMM: 64x128 tile, 256 threads, 4-stage (R11 config)
// ---------------------------------------------------------------------------
#define BKH 32
#define LDT 40
#define HG_STAGES 4
#define HG_A_HALVES (64  * LDT)
#define HG_B_HALVES (128 * LDT)
#define HG_SMEM_BYTES (HG_STAGES * (HG_A_HALVES + HG_B_HALVES) * 2)

template<int MODE>
__global__ __launch_bounds__(256)
void hgemm(const __half* __restrict__ A, const __half* __restrict__ Bm,
           float* __restrict__ C, int M, int N, int K,
           const float* __restrict__ bias,
           const float* __restrict__ bQv,
           const float* __restrict__ bKv,
           const float* __restrict__ bVv)
{
    grid_dep_sync();   // PDL: wait for producer kernels' data

    extern __shared__ __half smh[];
    __half* Asm = smh;
    __half* Bsm = smh + HG_STAGES * HG_A_HALVES;

    const int tid  = threadIdx.x;
    const int warp = tid >> 5, lane = tid & 31;
    const int wm = warp >> 2, wn = warp & 3;
    const int bm = blockIdx.y * 64, bn = blockIdx.x * 128;

    const int arow = tid >> 2;
    const int aoff = (tid & 3) * 8;
    const int brow = tid >> 1;
    const int boff = (tid & 1) * 16;

    const __half* Ag = A + (size_t)(bm + arow) * K + aoff;
    const __half* Bg = Bm + (size_t)(bn + brow) * K + boff;
    const uint32_t AsB = smem_u32(Asm);
    const uint32_t BsB = smem_u32(Bsm);
    const uint32_t stA = (uint32_t)(arow * LDT + aoff) * 2;
    const uint32_t stB = (uint32_t)(brow * LDT + boff) * 2;
    const uint32_t SA = HG_A_HALVES * 2;
    const uint32_t SB = HG_B_HALVES * 2;

    const int mat = lane >> 3, r = lane & 7;
    const uint32_t a_off = (uint32_t)((wm * 32 + (mat & 1) * 8 + r) * LDT + (mat >> 1) * 8) * 2;
    const uint32_t b_off = (uint32_t)((wn * 32 + (mat >> 1) * 8 + r) * LDT + (mat & 1) * 8) * 2;

    float acc[2][4][4];
#pragma unroll
    for (int i = 0; i < 2; i++)
#pragma unroll
        for (int j = 0; j < 4; j++)
#pragma unroll
            for (int tt = 0; tt < 4; tt++) acc[i][j][tt] = 0.f;

    const int KT = K / BKH;

#pragma unroll
    for (int s = 0; s < 3; s++) {
        cp16(AsB + s * SA + stA,      Ag + s * BKH);
        cp16(BsB + s * SB + stB,      Bg + s * BKH);
        cp16(BsB + s * SB + stB + 16, Bg + s * BKH + 8);
        asm volatile("cp.async.commit_group;");
    }
    asm volatile("cp.async.wait_group 2;" ::: "memory");
    __syncthreads();

    int stage = 0;
    for (int kt = 0; kt < KT; kt++) {
        const uint32_t Abuf = AsB + (uint32_t)stage * SA;
        const uint32_t Bbuf = BsB + (uint32_t)stage * SB;
#pragma unroll
        for (int ks = 0; ks < 2; ks++) {
            uint32_t a[2][4];
#pragma unroll
            for (int mt = 0; mt < 2; mt++)
                ldm4(a[mt][0], a[mt][1], a[mt][2], a[mt][3],
                     Abuf + a_off + (uint32_t)(mt * 16 * LDT + ks * 16) * 2);
            uint32_t bf[4][2];
#pragma unroll
            for (int p = 0; p < 2; p++) {
                uint32_t r0, r1, r2, r3;
                ldm4(r0, r1, r2, r3,
                     Bbuf + b_off + (uint32_t)(p * 16 * LDT + ks * 16) * 2);
                bf[2 * p][0] = r0; bf[2 * p][1] = r1;
                bf[2 * p + 1][0] = r2; bf[2 * p + 1][1] = r3;
            }
#pragma unroll
            for (int mt = 0; mt < 2; mt++)
#pragma unroll
                for (int nt = 0; nt < 4; nt++)
                    mma16816(acc[mt][nt], a[mt], bf[nt]);
        }

        if (kt + 3 < KT) {
            const int ns = (stage + 3 >= HG_STAGES) ? stage + 3 - HG_STAGES : stage + 3;
            const __half* ag = Ag + (kt + 3) * BKH;
            const __half* bg = Bg + (kt + 3) * BKH;
            cp16(AsB + (uint32_t)ns * SA + stA,      ag);
            cp16(BsB + (uint32_t)ns * SB + stB,      bg);
            cp16(BsB + (uint32_t)ns * SB + stB + 16, bg + 8);
            asm volatile("cp.async.commit_group;");
            asm volatile("cp.async.wait_group 2;" ::: "memory");
        } else {
            asm volatile("cp.async.wait_group 0;" ::: "memory");
        }
        __syncthreads();
        stage = (stage + 1 >= HG_STAGES) ? 0 : stage + 1;
    }

    if (MODE == 0) {
#pragma unroll
        for (int mt = 0; mt < 2; mt++) {
            const int r0 = bm + wm * 32 + mt * 16 + (lane >> 2);
#pragma unroll
            for (int nt = 0; nt < 4; nt++) {
                const int c0 = bn + wn * 32 + nt * 8 + (lane & 3) * 2;
                float b0 = bias[c0], b1 = bias[c0 + 1];
                float2 v01 = { acc[mt][nt][0] + b0, acc[mt][nt][1] + b1 };
                float2 v23 = { acc[mt][nt][2] + b0, acc[mt][nt][3] + b1 };
                *(float2*)(C + (size_t)r0 * N + c0)       = v01;
                *(float2*)(C + (size_t)(r0 + 8) * N + c0) = v23;
            }
        }
    } else {
        const int i = (lane & 3) * 2;
#pragma unroll
        for (int mt = 0; mt < 2; mt++) {
            const int r0 = bm + wm * 32 + mt * 16 + (lane >> 2);
#pragma unroll
            for (int rr = 0; rr < 2; rr++) {
                const int row = r0 + rr * 8;
                const int s = row & (S_ - 1);
                const int b = row >> 11;
                const float* rt = &g_rot[s * 16];
#pragma unroll
                for (int np = 0; np < 2; np++) {
                    const int base = bn + wn * 32 + np * 16;
                    const float vlo0 = acc[mt][2 * np][2 * rr + 0];
                    const float vlo1 = acc[mt][2 * np][2 * rr + 1];
                    const float vhi0 = acc[mt][2 * np + 1][2 * rr + 0];
                    const float vhi1 = acc[mt][2 * np + 1][2 * rr + 1];
                    if (base < 256) {
                        const int h = base >> 4;
                        float a0 = vlo0 + bQv[h * 16 + i];
                        float a1 = vlo1 + bQv[h * 16 + i + 1];
                        float c0 = vhi0 + bQv[h * 16 + i + 8];
                        float c1 = vhi1 + bQv[h * 16 + i + 9];
                        float sn0 = rt[i], sn1 = rt[i + 1];
                        float cs0 = rt[8 + i], cs1 = rt[9 + i];
                        __half* dst = &g_Qh[((size_t)(b * NQK_ + h) * S_ + s) * DQK_];
                        *(__half2*)&dst[i]     = __floats2half2_rn((a0 * cs0 - c0 * sn0) * QSCALE,
                                                                   (a1 * cs1 - c1 * sn1) * QSCALE);
                        *(__half2*)&dst[i + 8] = __floats2half2_rn((c0 * cs0 + a0 * sn0) * QSCALE,
                                                                   (c1 * cs1 + a1 * sn1) * QSCALE);
                    } else if (base < 512) {
                        const int h = (base - 256) >> 4;
                        float a0 = vlo0 + bKv[h * 16 + i];
                        float a1 = vlo1 + bKv[h * 16 + i + 1];
                        float c0 = vhi0 + bKv[h * 16 + i + 8];
                        float c1 = vhi1 + bKv[h * 16 + i + 9];
                        float sn0 = rt[i], sn1 = rt[i + 1];
                        float cs0 = rt[8 + i], cs1 = rt[9 + i];
                        __half* dst = &g_Kh[((size_t)(b * NQK_ + h) * SK_ + s) * DQK_];
                        *(__half2*)&dst[i]     = __floats2half2_rn(a0 * cs0 - c0 * sn0,
                                                                   a1 * cs1 - c1 * sn1);
                        *(__half2*)&dst[i + 8] = __floats2half2_rn(c0 * cs0 + a0 * sn0,
                                                                   c1 * cs1 + a1 * sn1);
                    } else {
                        const int n0 = base - 512;
                        const int h = n0 >> 4;
                        __half* dst = &g_Vh[((size_t)(b * NQK_ + h) * SK_ + s) * DQK_];
                        *(__half2*)&dst[i]     = __floats2half2_rn(vlo0 + bVv[n0 + i],
                                                                   vlo1 + bVv[n0 + i + 1]);
                        *(__half2*)&dst[i + 8] = __floats2half2_rn(vhi0 + bVv[n0 + i + 8],
                                                                   vhi1 + bVv[n0 + i + 9]);
                    }
                }
            }
        }
    }
}

// ---------------------------------------------------------------------------
// 3) Flash attention (exact R11/R15 champion version)
// ---------------------------------------------------------------------------
#define PAD 24

__global__ __launch_bounds__(128, 5)
void attn_mma()
{
    grid_dep_sync();   // PDL: wait for GEMM1's Q/K/V

    const int bh   = blockIdx.y;
    const int pp   = blockIdx.x;          // 0..15
    const int tid  = threadIdx.x;
    const int warp = tid >> 5, lane = tid & 31;

    __shared__ __half Qs[64 * PAD];
    __shared__ __half K0s[16 * PAD];
    __shared__ __half V0s[16 * PAD];
    __shared__ __half Ks[2][128 * PAD];
    __shared__ __half Vs[2][128 * PAD];

    const __half* Kg = g_Kh + (size_t)bh * SK_ * DQK_;
    const __half* Vg = g_Vh + (size_t)bh * SK_ * DQK_;

    const int ld_row = tid >> 1;
    const int ld_off = (tid & 1) * 8;

    if (tid < 32) {
        int pr = tid >> 1, po = (tid & 1) * 8;
        cp16(smem_u32(&K0s[pr * PAD + po]), Kg + (size_t)pr * 16 + po);
        cp16(smem_u32(&V0s[pr * PAD + po]), Vg + (size_t)pr * 16 + po);
    }
    asm volatile("cp.async.commit_group;");

    const int g = lane >> 3, r = lane & 7;
    const int qfrow = warp * 16 + (g & 1) * 8 + r;
    const int qfcol = (g >> 1) * 8;
    const int krow = (g >> 1) * 8 + r;
    const int kcol = (g & 1) * 8;
    const int vrow = (g & 1) * 8 + r;
    const int vcol = (g >> 1) * 8;
    const uint32_t onesb[2] = { 0x3C003C00u, 0x3C003C00u };

#pragma unroll 1
    for (int sel = 0; sel < 2; sel++) {
        const int qt = sel ? pp : (31 - pp);
        const int q0 = qt * 64;
        const __half* Qg = g_Qh + ((size_t)bh * S_ + q0) * DQK_;

        __syncthreads();

        *(float4*)&Qs[ld_row * PAD + ld_off] =
            *(const float4*)&Qg[(size_t)ld_row * 16 + ld_off];

        cp16(smem_u32(&Ks[0][ld_row * PAD + ld_off]),        Kg + (size_t)(16 + ld_row) * 16 + ld_off);
        cp16(smem_u32(&Ks[0][(ld_row + 64) * PAD + ld_off]), Kg + (size_t)(80 + ld_row) * 16 + ld_off);
        cp16(smem_u32(&Vs[0][ld_row * PAD + ld_off]),        Vg + (size_t)(16 + ld_row) * 16 + ld_off);
        cp16(smem_u32(&Vs[0][(ld_row + 64) * PAD + ld_off]), Vg + (size_t)(80 + ld_row) * 16 + ld_off);
        asm volatile("cp.async.commit_group;");

        asm volatile("cp.async.wait_group 1;" ::: "memory");
        __syncthreads();

        uint32_t qa[4];
        ldm4(qa[0], qa[1], qa[2], qa[3], smem_u32(&Qs[qfrow * PAD + qfcol]));

        float m0, m1;
        float o[2][4] = {{0.f,0.f,0.f,0.f},{0.f,0.f,0.f,0.f}};
        float oL[4]   = {0.f,0.f,0.f,0.f};

        // ---- prologue: 16 keys, unmasked ----
        {
            float sc[2][4] = {{0.f,0.f,0.f,0.f},{0.f,0.f,0.f,0.f}};
            uint32_t b0, b1, b2, b3;
            ldm4(b0, b1, b2, b3, smem_u32(&K0s[krow * PAD + kcol]));
            {
                uint32_t bl[2] = { b0, b1 }, bh2[2] = { b2, b3 };
                mma16816(sc[0], qa, bl);
                mma16816(sc[1], qa, bh2);
            }
            float rm0 = fmaxf(fmaxf(sc[0][0], sc[0][1]), fmaxf(sc[1][0], sc[1][1]));
            float rm1 = fmaxf(fmaxf(sc[0][2], sc[0][3]), fmaxf(sc[1][2], sc[1][3]));
            rm0 = fmaxf(rm0, __shfl_xor_sync(0xffffffff, rm0, 1));
            rm0 = fmaxf(rm0, __shfl_xor_sync(0xffffffff, rm0, 2));
            rm1 = fmaxf(rm1, __shfl_xor_sync(0xffffffff, rm1, 1));
            rm1 = fmaxf(rm1, __shfl_xor_sync(0xffffffff, rm1, 2));
            m0 = rm0; m1 = rm1;

            uint32_t pa[4];
            pa[0] = ex2h2(sc[0][0] - m0, sc[0][1] - m0);
            pa[1] = ex2h2(sc[0][2] - m1, sc[0][3] - m1);
            pa[2] = ex2h2(sc[1][0] - m0, sc[1][1] - m0);
            pa[3] = ex2h2(sc[1][2] - m1, sc[1][3] - m1);

            uint32_t v0, v1, v2, v3;
            ldm4t(v0, v1, v2, v3, smem_u32(&V0s[vrow * PAD + vcol]));
            uint32_t bl[2] = { v0, v1 }, bh2[2] = { v2, v3 };
            mma16816(o[0], pa, bl);
            mma16816(o[1], pa, bh2);
            mma16816(oL,   pa, onesb);
        }

        const int jmax = (q0 + 63) >> 7;

        for (int jt = 0; jt <= jmax; jt++) {
            const int buf = jt & 1;
            if (jt < jmax) {
                const size_t kb = (size_t)(16 + (jt + 1) * 128);
                cp16(smem_u32(&Ks[buf ^ 1][ld_row * PAD + ld_off]),        Kg + (kb + ld_row) * 16 + ld_off);
                cp16(smem_u32(&Ks[buf ^ 1][(ld_row + 64) * PAD + ld_off]), Kg + (kb + ld_row + 64) * 16 + ld_off);
                cp16(smem_u32(&Vs[buf ^ 1][ld_row * PAD + ld_off]),        Vg + (kb + ld_row) * 16 + ld_off);
                cp16(smem_u32(&Vs[buf ^ 1][(ld_row + 64) * PAD + ld_off]), Vg + (kb + ld_row + 64) * 16 + ld_off);
                asm volatile("cp.async.commit_group;");
                asm volatile("cp.async.wait_group 1;" ::: "memory");
            } else {
                asm volatile("cp.async.wait_group 0;" ::: "memory");
            }
            __syncthreads();

            if (jt < jmax) {
                // ===== FULL TILE: 128 keys, single softmax update =====
                float sc[16][4];
#pragma unroll
                for (int nt = 0; nt < 16; nt++)
#pragma unroll
                    for (int tt = 0; tt < 4; tt++) sc[nt][tt] = 0.f;

#pragma unroll
                for (int i = 0; i < 8; i++) {
                    uint32_t b0, b1, b2, b3;
                    ldm4(b0, b1, b2, b3,
                         smem_u32(&Ks[buf][(16 * i + krow) * PAD + kcol]));
                    uint32_t bl[2] = { b0, b1 }, bh2[2] = { b2, b3 };
                    mma16816(sc[2 * i],     qa, bl);
                    mma16816(sc[2 * i + 1], qa, bh2);
                }

                float rm0 = sc[0][0], rm1 = sc[0][2];
#pragma unroll
                for (int nt = 0; nt < 16; nt++) {
                    rm0 = fmaxf(rm0, fmaxf(sc[nt][0], sc[nt][1]));
                    rm1 = fmaxf(rm1, fmaxf(sc[nt][2], sc[nt][3]));
                }
                rm0 = fmaxf(rm0, __shfl_xor_sync(0xffffffff, rm0, 1));
                rm0 = fmaxf(rm0, __shfl_xor_sync(0xffffffff, rm0, 2));
                rm1 = fmaxf(rm1, __shfl_xor_sync(0xffffffff, rm1, 1));
                rm1 = fmaxf(rm1, __shfl_xor_sync(0xffffffff, rm1, 2));

                const float mn0 = fmaxf(m0, rm0);
                const float mn1 = fmaxf(m1, rm1);
                const float c0 = ex2f(m0 - mn0);
                const float c1 = ex2f(m1 - mn1);
                m0 = mn0; m1 = mn1;
                o[0][0] *= c0; o[0][1] *= c0; o[0][2] *= c1; o[0][3] *= c1;
                o[1][0] *= c0; o[1][1] *= c0; o[1][2] *= c1; o[1][3] *= c1;
                oL[0]   *= c0; oL[1]   *= c0; oL[2]   *= c1; oL[3]   *= c1;

#pragma unroll
                for (int kt = 0; kt < 8; kt++) {
                    uint32_t pa[4];
                    pa[0] = ex2h2(sc[2 * kt][0] - mn0,     sc[2 * kt][1] - mn0);
                    pa[1] = ex2h2(sc[2 * kt][2] - mn1,     sc[2 * kt][3] - mn1);
                    pa[2] = ex2h2(sc[2 * kt + 1][0] - mn0, sc[2 * kt + 1][1] - mn0);
                    pa[3] = ex2h2(sc[2 * kt + 1][2] - mn1, sc[2 * kt + 1][3] - mn1);
                    uint32_t v0, v1, v2, v3;
                    ldm4t(v0, v1, v2, v3,
                          smem_u32(&Vs[buf][(16 * kt + vrow) * PAD + vcol]));
                    uint32_t bl[2] = { v0, v1 }, bh2[2] = { v2, v3 };
                    mma16816(o[0], pa, bl);
                    mma16816(o[1], pa, bh2);
                    mma16816(oL,   pa, onesb);
                }
                __syncthreads();
            } else {
                // ===== DIAG TILE: chunked + warp-uniform skips + mask =====
                const int off = q0 - 128 * jt;
                const int wb  = off + warp * 16 + 15;

#pragma unroll
                for (int c = 0; c < 2; c++) {
                    if (c * 64 <= wb) {
                        float sc[8][4];
#pragma unroll
                        for (int nt = 0; nt < 8; nt++)
#pragma unroll
                            for (int tt = 0; tt < 4; tt++) sc[nt][tt] = 0.f;

#pragma unroll
                        for (int i = 0; i < 4; i++) {
                            if ((c * 64 + i * 16) <= wb) {
                                uint32_t b0, b1, b2, b3;
                                ldm4(b0, b1, b2, b3,
                                     smem_u32(&Ks[buf][(16 * (c * 4 + i) + krow) * PAD + kcol]));
                                uint32_t bl[2] = { b0, b1 }, bh2[2] = { b2, b3 };
                                mma16816(sc[2 * i],     qa, bl);
                                mma16816(sc[2 * i + 1], qa, bh2);
                            }
                        }

                        {
                            const int jb = c * 64 + (lane & 3) * 2;
                            const int t0 = off + warp * 16 + (lane >> 2);
                            const int t1 = t0 + 8;
#pragma unroll
                            for (int nt = 0; nt < 8; nt++) {
                                int j0 = jb + nt * 8;
                                if (j0     > t0) sc[nt][0] = -1e30f;
                                if (j0 + 1 > t0) sc[nt][1] = -1e30f;
                                if (j0     > t1) sc[nt][2] = -1e30f;
                                if (j0 + 1 > t1) sc[nt][3] = -1e30f;
                            }
                        }

                        float rm0 = sc[0][0], rm1 = sc[0][2];
#pragma unroll
                        for (int nt = 0; nt < 8; nt++) {
                            rm0 = fmaxf(rm0, fmaxf(sc[nt][0], sc[nt][1]));
                            rm1 = fmaxf(rm1, fmaxf(sc[nt][2], sc[nt][3]));
                        }
                        rm0 = fmaxf(rm0, __shfl_xor_sync(0xffffffff, rm0, 1));
                        rm0 = fmaxf(rm0, __shfl_xor_sync(0xffffffff, rm0, 2));
                        rm1 = fmaxf(rm1, __shfl_xor_sync(0xffffffff, rm1, 1));
                        rm1 = fmaxf(rm1, __shfl_xor_sync(0xffffffff, rm1, 2));

                        const float mn0 = fmaxf(m0, rm0);
                        const float mn1 = fmaxf(m1, rm1);
                        const float c0 = ex2f(m0 - mn0);
                        const float c1 = ex2f(m1 - mn1);
                        m0 = mn0; m1 = mn1;
                        o[0][0] *= c0; o[0][1] *= c0; o[0][2] *= c1; o[0][3] *= c1;
                        o[1][0] *= c0; o[1][1] *= c0; o[1][2] *= c1; o[1][3] *= c1;
                        oL[0]   *= c0; oL[1]   *= c0; oL[2]   *= c1; oL[3]   *= c1;

#pragma unroll
                        for (int kt = 0; kt < 4; kt++) {
                            if ((c * 64 + kt * 16) <= wb) {
                                uint32_t pa[4];
                                pa[0] = ex2h2(sc[2 * kt][0] - mn0,     sc[2 * kt][1] - mn0);
                                pa[1] = ex2h2(sc[2 * kt][2] - mn1,     sc[2 * kt][3] - mn1);
                                pa[2] = ex2h2(sc[2 * kt + 1][0] - mn0, sc[2 * kt + 1][1] - mn0);
                                pa[3] = ex2h2(sc[2 * kt + 1][2] - mn1, sc[2 * kt + 1][3] - mn1);
                                uint32_t v0, v1, v2, v3;
                                ldm4t(v0, v1, v2, v3,
                                      smem_u32(&Vs[buf][(16 * (c * 4 + kt) + vrow) * PAD + vcol]));
                                uint32_t bl[2] = { v0, v1 }, bh2[2] = { v2, v3 };
                                mma16816(o[0], pa, bl);
                                mma16816(o[1], pa, bh2);
                                mma16816(oL,   pa, onesb);
                            }
                        }
                    }
                }
                __syncthreads();
            }
        }

        const float inv0 = 1.f / oL[0];
        const float inv1 = 1.f / oL[2];

        const int qrow0 = q0 + warp * 16 + (lane >> 2);
        const int b = bh >> 4, h = bh & 15;
        const int col = (lane & 3) * 2;
#pragma unroll
        for (int vt = 0; vt < 2; vt++) {
            uint32_t lo = packh2(o[vt][0] * inv0, o[vt][1] * inv0);
            uint32_t hi = packh2(o[vt][2] * inv1, o[vt][3] * inv1);
            size_t base0 = ((size_t)(b * S_ + qrow0)     ) * NOV_ + h * 16 + vt * 8 + col;
            size_t base1 = ((size_t)(b * S_ + qrow0 + 8) ) * NOV_ + h * 16 + vt * 8 + col;
            *(uint32_t*)&g_Zh[base0] = lo;
            *(uint32_t*)&g_Zh[base1] = hi;
        }
    }
}

// ---------------------------------------------------------------------------
// Launch (PDL: dependent kernels launch-overlap with producer tails;
//         prep_rest runs concurrently with prep_core)
// ---------------------------------------------------------------------------
template<typename F, typename... Args>
static void launch_pdl(F func, dim3 grid, dim3 block, size_t smem, Args... args)
{
    cudaLaunchConfig_t cfg = {};
    cfg.gridDim = grid;
    cfg.blockDim = block;
    cfg.dynamicSmemBytes = smem;
    cfg.stream = 0;
    cudaLaunchAttribute attr[1];
    attr[0].id = cudaLaunchAttributeProgrammaticStreamSerialization;
    attr[0].val.programmaticStreamSerializationAllowed = 1;
    cfg.attrs = attr;
    cfg.numAttrs = 1;
    cudaLaunchKernelEx(&cfg, func, args...);
}

extern "C" void kernel_launch(void* const* d_in, const int* in_sizes, int n_in,
                              void* d_out, int out_size)
{
    const float* resid = (const float*)d_in[0];
    const float* W_Q   = (const float*)d_in[1];
    const float* W_K   = (const float*)d_in[2];
    const float* W_V   = (const float*)d_in[3];
    const float* W_O   = (const float*)d_in[4];
    const float* b_Q   = (const float*)d_in[5];
    const float* b_K   = (const float*)d_in[6];
    const float* b_V   = (const float*)d_in[7];
    const float* b_O   = (const float*)d_in[8];
    const float* v_k   = (const float*)d_in[9];
    const float* v_v   = (const float*)d_in[10];
    float* out = (float*)d_out;

    __half *Ah, *Wh1, *Wh2, *Zh;
    cudaGetSymbolAddress((void**)&Ah,  g_Ah);
    cudaGetSymbolAddress((void**)&Wh1, g_Wh1);
    cudaGetSymbolAddress((void**)&Wh2, g_Wh2);
    cudaGetSymbolAddress((void**)&Zh,  g_Zh);

    cudaFuncSetAttribute(hgemm<0>, cudaFuncAttributeMaxDynamicSharedMemorySize, HG_SMEM_BYTES);
    cudaFuncSetAttribute(hgemm<1>, cudaFuncAttributeMaxDynamicSharedMemorySize, HG_SMEM_BYTES);

    // 1a) prep_core (Wh1 + Ah) — triggers early so prep_rest can overlap
    prep_core<<<PC_BLKS, 256>>>(W_Q, W_K, W_V, resid);

    // 1b) prep_rest (Wh2 + rot + virtual KV) — PDL, no grid sync -> concurrent
    launch_pdl(prep_rest, dim3(PR_BLKS), dim3(256), (size_t)0, W_O, v_k, v_v);

    // 2) GEMM1 + fused bias/rotary/scatter epilogue -> g_Qh/g_Kh/g_Vh
    launch_pdl(hgemm<1>, dim3(DM_ / 128, BS_ / 64), dim3(256), (size_t)HG_SMEM_BYTES,
               (const __half*)Ah, (const __half*)Wh1, (float*)nullptr, BS_, DM_, DM_,
               (const float*)nullptr, b_Q, b_K, b_V);

    // 3) tensor-core flash attention
    launch_pdl(attn_mma, dim3(16, B_ * NQK_), dim3(128), (size_t)0);

    // 4) GEMM2: (4096 x 768) = Zh * Wh2^T + b_O -> out fp32
    launch_pdl(hgemm<0>, dim3(DM_ / 128, BS_ / 64), dim3(256), (size_t)HG_SMEM_BYTES,
               (const __half*)Zh, (const __half*)Wh2, out, BS_, DM_, NOV_,
               b_O, (const float*)nullptr, (const float*)nullptr, (const float*)nullptr);
}

// round 17
// speedup vs baseline: 1.0251x; 1.0251x over previous
#include <cuda_runtime.h>
#include <cuda_fp16.h>
#include <cstdint>

// ---------------------------------------------------------------------------
// Problem constants
// ---------------------------------------------------------------------------
#define B_   2
#define S_   2048
#define DM_  768
#define NQK_ 16
#define DQK_ 16
#define NOV_ 256
#define VKV_ 16
#define SK_  (S_ + VKV_)     // 2064 keys = 16 + 16*128 (exact)
#define BS_  (B_ * S_)       // 4096 rows

// ---------------------------------------------------------------------------
// Device scratch
// ---------------------------------------------------------------------------
__device__ __half g_Ah  [BS_ * DM_];
__device__ __half g_Wh1 [DM_ * DM_];
__device__ __half g_Wh2 [DM_ * NOV_];
__device__ float  g_rot [S_ * 16];                  // [s][0..7]=sin, [8..15]=cos
__device__ __half g_Qh  [B_ * NQK_ * S_  * DQK_];
__device__ __half g_Kh  [B_ * NQK_ * SK_ * DQK_];
__device__ __half g_Vh  [B_ * NQK_ * SK_ * DQK_];
__device__ __half g_Zh  [BS_ * NOV_];

// ---------------------------------------------------------------------------
// helpers
// ---------------------------------------------------------------------------
__device__ __forceinline__ void grid_dep_sync() {
#if __CUDA_ARCH__ >= 900
    cudaGridDependencySynchronize();
#endif
}
__device__ __forceinline__ void trigger_dep_launch() {
#if __CUDA_ARCH__ >= 900
    cudaTriggerProgrammaticLaunchCompletion();
#endif
}
__device__ __forceinline__ uint32_t smem_u32(const void* p) {
    return (uint32_t)__cvta_generic_to_shared(p);
}
__device__ __forceinline__ void cp16(uint32_t s, const void* g) {
    asm volatile("cp.async.cg.shared.global [%0], [%1], 16;" :: "r"(s), "l"(g));
}
__device__ __forceinline__ float ex2f(float x) {
    float y; asm("ex2.approx.ftz.f32 %0, %1;" : "=f"(y) : "f"(x)); return y;
}
__device__ __forceinline__ uint32_t ex2h2(float lo, float hi) {
    uint32_t h, r;
    asm("cvt.rn.f16x2.f32 %0, %1, %2;" : "=r"(h) : "f"(hi), "f"(lo));
    asm("ex2.approx.f16x2 %0, %1;" : "=r"(r) : "r"(h));
    return r;
}
__device__ __forceinline__ void ldm4(uint32_t& r0, uint32_t& r1, uint32_t& r2, uint32_t& r3, uint32_t addr) {
    asm volatile("ldmatrix.sync.aligned.m8n8.x4.shared.b16 {%0,%1,%2,%3}, [%4];"
                 : "=r"(r0), "=r"(r1), "=r"(r2), "=r"(r3) : "r"(addr));
}
__device__ __forceinline__ void ldm4t(uint32_t& r0, uint32_t& r1, uint32_t& r2, uint32_t& r3, uint32_t addr) {
    asm volatile("ldmatrix.sync.aligned.m8n8.x4.trans.shared.b16 {%0,%1,%2,%3}, [%4];"
                 : "=r"(r0), "=r"(r1), "=r"(r2), "=r"(r3) : "r"(addr));
}
__device__ __forceinline__ void mma16816(float* d, const uint32_t* a, const uint32_t* b) {
    asm volatile("mma.sync.aligned.m16n8k16.row.col.f32.f16.f16.f32 "
                 "{%0,%1,%2,%3},{%4,%5,%6,%7},{%8,%9},{%0,%1,%2,%3};"
                 : "+f"(d[0]), "+f"(d[1]), "+f"(d[2]), "+f"(d[3])
                 : "r"(a[0]), "r"(a[1]), "r"(a[2]), "r"(a[3]), "r"(b[0]), "r"(b[1]));
}
__device__ __forceinline__ uint32_t packh2(float x, float y) {
    __half2 h = __floats2half2_rn(x, y);
    return *(uint32_t*)&h;
}

#define QSCALE 0.36067376022224085f   // 0.25 * log2(e)
#define PAD 24

// ---------------------------------------------------------------------------
// attention tile bodies (verbatim champion math, functionized)
// ---------------------------------------------------------------------------
__device__ __forceinline__ void qmaxred(float& rm0, float& rm1) {
    rm0 = fmaxf(rm0, __shfl_xor_sync(0xffffffff, rm0, 1));
    rm0 = fmaxf(rm0, __shfl_xor_sync(0xffffffff, rm0, 2));
    rm1 = fmaxf(rm1, __shfl_xor_sync(0xffffffff, rm1, 1));
    rm1 = fmaxf(rm1, __shfl_xor_sync(0xffffffff, rm1, 2));
}

// 16-key unmasked tile (prologue); general rescale path (zero-state safe)
__device__ __forceinline__ void attn_tile16(
    const uint32_t* qa, float& m0, float& m1, float o[2][4], float* oL,
    uint32_t kaddr, uint32_t vaddr, const uint32_t* onesb)
{
    float sc[2][4] = {{0.f,0.f,0.f,0.f},{0.f,0.f,0.f,0.f}};
    uint32_t b0, b1, b2, b3;
    ldm4(b0, b1, b2, b3, kaddr);
    {
        uint32_t bl[2] = { b0, b1 }, bh2[2] = { b2, b3 };
        mma16816(sc[0], qa, bl);
        mma16816(sc[1], qa, bh2);
    }
    float rm0 = fmaxf(fmaxf(sc[0][0], sc[0][1]), fmaxf(sc[1][0], sc[1][1]));
    float rm1 = fmaxf(fmaxf(sc[0][2], sc[0][3]), fmaxf(sc[1][2], sc[1][3]));
    qmaxred(rm0, rm1);
    const float mn0 = fmaxf(m0, rm0);
    const float mn1 = fmaxf(m1, rm1);
    const float c0 = ex2f(m0 - mn0);
    const float c1 = ex2f(m1 - mn1);
    m0 = mn0; m1 = mn1;
    o[0][0] *= c0; o[0][1] *= c0; o[0][2] *= c1; o[0][3] *= c1;
    o[1][0] *= c0; o[1][1] *= c0; o[1][2] *= c1; o[1][3] *= c1;
    oL[0]   *= c0; oL[1]   *= c0; oL[2]   *= c1; oL[3]   *= c1;

    uint32_t pa[4];
    pa[0] = ex2h2(sc[0][0] - mn0, sc[0][1] - mn0);
    pa[1] = ex2h2(sc[0][2] - mn1, sc[0][3] - mn1);
    pa[2] = ex2h2(sc[1][0] - mn0, sc[1][1] - mn0);
    pa[3] = ex2h2(sc[1][2] - mn1, sc[1][3] - mn1);

    uint32_t v0, v1, v2, v3;
    ldm4t(v0, v1, v2, v3, vaddr);
    uint32_t bl[2] = { v0, v1 }, bh2[2] = { v2, v3 };
    mma16816(o[0], pa, bl);
    mma16816(o[1], pa, bh2);
    mma16816(oL,   pa, onesb);
}

// 128-key full tile, single softmax update
__device__ __forceinline__ void attn_full_tile(
    const uint32_t* qa, float& m0, float& m1, float o[2][4], float* oL,
    uint32_t kaddr, uint32_t vaddr, const uint32_t* onesb)
{
    float sc[16][4];
#pragma unroll
    for (int nt = 0; nt < 16; nt++)
#pragma unroll
        for (int tt = 0; tt < 4; tt++) sc[nt][tt] = 0.f;

#pragma unroll
    for (int i = 0; i < 8; i++) {
        uint32_t b0, b1, b2, b3;
        ldm4(b0, b1, b2, b3, kaddr + (uint32_t)(16 * i * PAD) * 2);
        uint32_t bl[2] = { b0, b1 }, bh2[2] = { b2, b3 };
        mma16816(sc[2 * i],     qa, bl);
        mma16816(sc[2 * i + 1], qa, bh2);
    }

    float rm0 = sc[0][0], rm1 = sc[0][2];
#pragma unroll
    for (int nt = 0; nt < 16; nt++) {
        rm0 = fmaxf(rm0, fmaxf(sc[nt][0], sc[nt][1]));
        rm1 = fmaxf(rm1, fmaxf(sc[nt][2], sc[nt][3]));
    }
    qmaxred(rm0, rm1);

    const float mn0 = fmaxf(m0, rm0);
    const float mn1 = fmaxf(m1, rm1);
    const float c0 = ex2f(m0 - mn0);
    const float c1 = ex2f(m1 - mn1);
    m0 = mn0; m1 = mn1;
    o[0][0] *= c0; o[0][1] *= c0; o[0][2] *= c1; o[0][3] *= c1;
    o[1][0] *= c0; o[1][1] *= c0; o[1][2] *= c1; o[1][3] *= c1;
    oL[0]   *= c0; oL[1]   *= c0; oL[2]   *= c1; oL[3]   *= c1;

#pragma unroll
    for (int kt = 0; kt < 8; kt++) {
        uint32_t pa[4];
        pa[0] = ex2h2(sc[2 * kt][0] - mn0,     sc[2 * kt][1] - mn0);
        pa[1] = ex2h2(sc[2 * kt][2] - mn1,     sc[2 * kt][3] - mn1);
        pa[2] = ex2h2(sc[2 * kt + 1][0] - mn0, sc[2 * kt + 1][1] - mn0);
        pa[3] = ex2h2(sc[2 * kt + 1][2] - mn1, sc[2 * kt + 1][3] - mn1);
        uint32_t v0, v1, v2, v3;
        ldm4t(v0, v1, v2, v3, vaddr + (uint32_t)(16 * kt * PAD) * 2);
        uint32_t bl[2] = { v0, v1 }, bh2[2] = { v2, v3 };
        mma16816(o[0], pa, bl);
        mma16816(o[1], pa, bh2);
        mma16816(oL,   pa, onesb);
    }
}

// diagonal tile: chunked + warp-uniform skips + causal mask
__device__ __forceinline__ void attn_diag_tile(
    const uint32_t* qa, float& m0, float& m1, float o[2][4], float* oL,
    uint32_t kaddr, uint32_t vaddr, const uint32_t* onesb,
    int off, int warp, int lane)
{
    const int wb = off + warp * 16 + 15;
#pragma unroll
    for (int c = 0; c < 2; c++) {
        if (c * 64 <= wb) {
            float sc[8][4];
#pragma unroll
            for (int nt = 0; nt < 8; nt++)
#pragma unroll
                for (int tt = 0; tt < 4; tt++) sc[nt][tt] = 0.f;

#pragma unroll
            for (int i = 0; i < 4; i++) {
                if ((c * 64 + i * 16) <= wb) {
                    uint32_t b0, b1, b2, b3;
                    ldm4(b0, b1, b2, b3,
                         kaddr + (uint32_t)(16 * (c * 4 + i) * PAD) * 2);
                    uint32_t bl[2] = { b0, b1 }, bh2[2] = { b2, b3 };
                    mma16816(sc[2 * i],     qa, bl);
                    mma16816(sc[2 * i + 1], qa, bh2);
                }
            }

            {
                const int jb = c * 64 + (lane & 3) * 2;
                const int t0 = off + warp * 16 + (lane >> 2);
                const int t1 = t0 + 8;
#pragma unroll
                for (int nt = 0; nt < 8; nt++) {
                    int j0 = jb + nt * 8;
                    if (j0     > t0) sc[nt][0] = -1e30f;
                    if (j0 + 1 > t0) sc[nt][1] = -1e30f;
                    if (j0     > t1) sc[nt][2] = -1e30f;
                    if (j0 + 1 > t1) sc[nt][3] = -1e30f;
                }
            }

            float rm0 = sc[0][0], rm1 = sc[0][2];
#pragma unroll
            for (int nt = 0; nt < 8; nt++) {
                rm0 = fmaxf(rm0, fmaxf(sc[nt][0], sc[nt][1]));
                rm1 = fmaxf(rm1, fmaxf(sc[nt][2], sc[nt][3]));
            }
            qmaxred(rm0, rm1);

            const float mn0 = fmaxf(m0, rm0);
            const float mn1 = fmaxf(m1, rm1);
            const float c0 = ex2f(m0 - mn0);
            const float c1 = ex2f(m1 - mn1);
            m0 = mn0; m1 = mn1;
            o[0][0] *= c0; o[0][1] *= c0; o[0][2] *= c1; o[0][3] *= c1;
            o[1][0] *= c0; o[1][1] *= c0; o[1][2] *= c1; o[1][3] *= c1;
            oL[0]   *= c0; oL[1]   *= c0; oL[2]   *= c1; oL[3]   *= c1;

#pragma unroll
            for (int kt = 0; kt < 4; kt++) {
                if ((c * 64 + kt * 16) <= wb) {
                    uint32_t pa[4];
                    pa[0] = ex2h2(sc[2 * kt][0] - mn0,     sc[2 * kt][1] - mn0);
                    pa[1] = ex2h2(sc[2 * kt][2] - mn1,     sc[2 * kt][3] - mn1);
                    pa[2] = ex2h2(sc[2 * kt + 1][0] - mn0, sc[2 * kt + 1][1] - mn0);
                    pa[3] = ex2h2(sc[2 * kt + 1][2] - mn1, sc[2 * kt + 1][3] - mn1);
                    uint32_t v0, v1, v2, v3;
                    ldm4t(v0, v1, v2, v3,
                          vaddr + (uint32_t)(16 * (c * 4 + kt) * PAD) * 2);
                    uint32_t bl[2] = { v0, v1 }, bh2[2] = { v2, v3 };
                    mma16816(o[0], pa, bl);
                    mma16816(o[1], pa, bh2);
                    mma16816(oL,   pa, onesb);
                }
            }
        }
    }
}

__device__ __forceinline__ void attn_epilogue(
    int q0, int bh, int warp, int lane, const float o[2][4], const float* oL)
{
    const float inv0 = 1.f / oL[0];
    const float inv1 = 1.f / oL[2];
    const int qrow0 = q0 + warp * 16 + (lane >> 2);
    const int b = bh >> 4, h = bh & 15;
    const int col = (lane & 3) * 2;
#pragma unroll
    for (int vt = 0; vt < 2; vt++) {
        uint32_t lo = packh2(o[vt][0] * inv0, o[vt][1] * inv0);
        uint32_t hi = packh2(o[vt][2] * inv1, o[vt][3] * inv1);
        size_t base0 = ((size_t)(b * S_ + qrow0)     ) * NOV_ + h * 16 + vt * 8 + col;
        size_t base1 = ((size_t)(b * S_ + qrow0 + 8) ) * NOV_ + h * 16 + vt * 8 + col;
        *(uint32_t*)&g_Zh[base0] = lo;
        *(uint32_t*)&g_Zh[base1] = hi;
    }
}

// ---------------------------------------------------------------------------
// 1a) prep_core (unchanged R16)
// ---------------------------------------------------------------------------
#define PC_V0   384
#define PC_CV0  1152
#define PC_BLKS 2688

__global__ void prep_core(const float* __restrict__ WQ,
                          const float* __restrict__ WK,
                          const float* __restrict__ WV,
                          const float* __restrict__ resid)
{
    trigger_dep_launch();
    __shared__ float sm[64 * 17];
    const int blk = blockIdx.x;
    const int t = threadIdx.x;

    if (blk < PC_V0) {
        int rem = blk, mat = rem / 192; rem %= 192;
        int h = rem / 12, d0 = (rem % 12) * 64;
        const float* W = mat ? WK : WQ;
        {
            int row = t >> 2, part = t & 3;
            float4 v = *(const float4*)&W[((size_t)h * DM_ + d0 + row) * DQK_ + part * 4];
            sm[row * 17 + part * 4 + 0] = v.x;
            sm[row * 17 + part * 4 + 1] = v.y;
            sm[row * 17 + part * 4 + 2] = v.z;
            sm[row * 17 + part * 4 + 3] = v.w;
        }
        __syncthreads();
        {
            int e = t >> 4, dcol = (t & 15) * 4;
            int c = mat * 256 + h * 16 + e;
            __half* dst = &g_Wh1[(size_t)c * DM_ + d0 + dcol];
            *(__half2*)&dst[0] = __floats2half2_rn(sm[(dcol + 0) * 17 + e], sm[(dcol + 1) * 17 + e]);
            *(__half2*)&dst[2] = __floats2half2_rn(sm[(dcol + 2) * 17 + e], sm[(dcol + 3) * 17 + e]);
        }
    } else if (blk < PC_CV0) {
        int idx = (blk - PC_V0) * 256 + t;
        g_Wh1[512 * DM_ + idx] = __float2half(WV[idx]);
    } else {
        int i = ((blk - PC_CV0) * 256 + t) * 8;
        float4 v0 = *(const float4*)(resid + i);
        float4 v1 = *(const float4*)(resid + i + 4);
        *(__half2*)&g_Ah[i]     = __floats2half2_rn(v0.x, v0.y);
        *(__half2*)&g_Ah[i + 2] = __floats2half2_rn(v0.z, v0.w);
        *(__half2*)&g_Ah[i + 4] = __floats2half2_rn(v1.x, v1.y);
        *(__half2*)&g_Ah[i + 6] = __floats2half2_rn(v1.z, v1.w);
    }
}

// ---------------------------------------------------------------------------
// 1b) prep_rest (unchanged R16)
// ---------------------------------------------------------------------------
#define PR_RT0  192
#define PR_VV0  256
#define PR_BLKS 288

__global__ void prep_rest(const float* __restrict__ WO,
                          const float* __restrict__ vk,
                          const float* __restrict__ vv)
{
    __shared__ float sm[64 * 17];
    const int blk = blockIdx.x;
    const int t = threadIdx.x;

    if (blk < PR_RT0) {
        int n0 = (blk / 12) * 16, m0 = (blk % 12) * 64;
        {
            int row = t >> 4, part = t & 15;
            float4 v = *(const float4*)&WO[(size_t)(n0 + row) * DM_ + m0 + part * 4];
            sm[row * 65 + part * 4 + 0] = v.x;
            sm[row * 65 + part * 4 + 1] = v.y;
            sm[row * 65 + part * 4 + 2] = v.z;
            sm[row * 65 + part * 4 + 3] = v.w;
        }
        __syncthreads();
        {
            int mm = t >> 2, nn = (t & 3) * 4;
            __half* dst = &g_Wh2[(size_t)(m0 + mm) * NOV_ + n0 + nn];
            *(__half2*)&dst[0] = __floats2half2_rn(sm[(nn + 0) * 65 + mm], sm[(nn + 1) * 65 + mm]);
            *(__half2*)&dst[2] = __floats2half2_rn(sm[(nn + 2) * 65 + mm], sm[(nn + 3) * 65 + mm]);
        }
    } else if (blk < PR_VV0) {
        int idx = (blk - PR_RT0) * 256 + t;
        int s = idx >> 3, i = idx & 7;
        float freq = powf(10000.f, (float)i / 8.f);
        float sn, cs;
        sincosf((float)s / freq, &sn, &cs);
        g_rot[s * 16 + i]     = sn;
        g_rot[s * 16 + 8 + i] = cs;
    } else {
        int idx = (blk - PR_VV0) * 256 + t;
        int c = idx & 255;
        int m = (idx >> 8) & 15;
        int b = idx >> 12;
        int h = c >> 4, e = c & 15;
        size_t row = ((size_t)(b * NQK_ + h) * SK_ + S_ + m) * DQK_ + e;
        g_Kh[row] = __float2half(vk[m * 256 + c]);
        g_Vh[row] = __float2half(vv[m * 256 + c]);
    }
}

// ---------------------------------------------------------------------------
// 2) fp16 tensor-core GEMM (unchanged R11/R16 config)
// ---------------------------------------------------------------------------
#define BKH 32
#define LDT 40
#define HG_STAGES 4
#define HG_A_HALVES (64  * LDT)
#define HG_B_HALVES (128 * LDT)
#define HG_SMEM_BYTES (HG_STAGES * (HG_A_HALVES + HG_B_HALVES) * 2)

template<int MODE>
__global__ __launch_bounds__(256)
void hgemm(const __half* __restrict__ A, const __half* __restrict__ Bm,
           float* __restrict__ C, int M, int N, int K,
           const float* __restrict__ bias,
           const float* __restrict__ bQv,
           const float* __restrict__ bKv,
           const float* __restrict__ bVv)
{
    grid_dep_sync();

    extern __shared__ __half smh[];
    __half* Asm = smh;
    __half* Bsm = smh + HG_STAGES * HG_A_HALVES;

    const int tid  = threadIdx.x;
    const int warp = tid >> 5, lane = tid & 31;
    const int wm = warp >> 2, wn = warp & 3;
    const int bm = blockIdx.y * 64, bn = blockIdx.x * 128;

    const int arow = tid >> 2;
    const int aoff = (tid & 3) * 8;
    const int brow = tid >> 1;
    const int boff = (tid & 1) * 16;

    const __half* Ag = A + (size_t)(bm + arow) * K + aoff;
    const __half* Bg = Bm + (size_t)(bn + brow) * K + boff;
    const uint32_t AsB = smem_u32(Asm);
    const uint32_t BsB = smem_u32(Bsm);
    const uint32_t stA = (uint32_t)(arow * LDT + aoff) * 2;
    const uint32_t stB = (uint32_t)(brow * LDT + boff) * 2;
    const uint32_t SA = HG_A_HALVES * 2;
    const uint32_t SB = HG_B_HALVES * 2;

    const int mat = lane >> 3, r = lane & 7;
    const uint32_t a_off = (uint32_t)((wm * 32 + (mat & 1) * 8 + r) * LDT + (mat >> 1) * 8) * 2;
    const uint32_t b_off = (uint32_t)((wn * 32 + (mat >> 1) * 8 + r) * LDT + (mat & 1) * 8) * 2;

    float acc[2][4][4];
#pragma unroll
    for (int i = 0; i < 2; i++)
#pragma unroll
        for (int j = 0; j < 4; j++)
#pragma unroll
            for (int tt = 0; tt < 4; tt++) acc[i][j][tt] = 0.f;

    const int KT = K / BKH;

#pragma unroll
    for (int s = 0; s < 3; s++) {
        cp16(AsB + s * SA + stA,      Ag + s * BKH);
        cp16(BsB + s * SB + stB,      Bg + s * BKH);
        cp16(BsB + s * SB + stB + 16, Bg + s * BKH + 8);
        asm volatile("cp.async.commit_group;");
    }
    asm volatile("cp.async.wait_group 2;" ::: "memory");
    __syncthreads();

    int stage = 0;
    for (int kt = 0; kt < KT; kt++) {
        const uint32_t Abuf = AsB + (uint32_t)stage * SA;
        const uint32_t Bbuf = BsB + (uint32_t)stage * SB;
#pragma unroll
        for (int ks = 0; ks < 2; ks++) {
            uint32_t a[2][4];
#pragma unroll
            for (int mt = 0; mt < 2; mt++)
                ldm4(a[mt][0], a[mt][1], a[mt][2], a[mt][3],
                     Abuf + a_off + (uint32_t)(mt * 16 * LDT + ks * 16) * 2);
            uint32_t bf[4][2];
#pragma unroll
            for (int p = 0; p < 2; p++) {
                uint32_t r0, r1, r2, r3;
                ldm4(r0, r1, r2, r3,
                     Bbuf + b_off + (uint32_t)(p * 16 * LDT + ks * 16) * 2);
                bf[2 * p][0] = r0; bf[2 * p][1] = r1;
                bf[2 * p + 1][0] = r2; bf[2 * p + 1][1] = r3;
            }
#pragma unroll
            for (int mt = 0; mt < 2; mt++)
#pragma unroll
                for (int nt = 0; nt < 4; nt++)
                    mma16816(acc[mt][nt], a[mt], bf[nt]);
        }

        if (kt + 3 < KT) {
            const int ns = (stage + 3 >= HG_STAGES) ? stage + 3 - HG_STAGES : stage + 3;
            const __half* ag = Ag + (kt + 3) * BKH;
            const __half* bg = Bg + (kt + 3) * BKH;
            cp16(AsB + (uint32_t)ns * SA + stA,      ag);
            cp16(BsB + (uint32_t)ns * SB + stB,      bg);
            cp16(BsB + (uint32_t)ns * SB + stB + 16, bg + 8);
            asm volatile("cp.async.commit_group;");
            asm volatile("cp.async.wait_group 2;" ::: "memory");
        } else {
            asm volatile("cp.async.wait_group 0;" ::: "memory");
        }
        __syncthreads();
        stage = (stage + 1 >= HG_STAGES) ? 0 : stage + 1;
    }

    if (MODE == 0) {
#pragma unroll
        for (int mt = 0; mt < 2; mt++) {
            const int r0 = bm + wm * 32 + mt * 16 + (lane >> 2);
#pragma unroll
            for (int nt = 0; nt < 4; nt++) {
                const int c0 = bn + wn * 32 + nt * 8 + (lane & 3) * 2;
                float b0 = bias[c0], b1 = bias[c0 + 1];
                float2 v01 = { acc[mt][nt][0] + b0, acc[mt][nt][1] + b1 };
                float2 v23 = { acc[mt][nt][2] + b0, acc[mt][nt][3] + b1 };
                *(float2*)(C + (size_t)r0 * N + c0)       = v01;
                *(float2*)(C + (size_t)(r0 + 8) * N + c0) = v23;
            }
        }
    } else {
        const int i = (lane & 3) * 2;
#pragma unroll
        for (int mt = 0; mt < 2; mt++) {
            const int r0 = bm + wm * 32 + mt * 16 + (lane >> 2);
#pragma unroll
            for (int rr = 0; rr < 2; rr++) {
                const int row = r0 + rr * 8;
                const int s = row & (S_ - 1);
                const int b = row >> 11;
                const float* rt = &g_rot[s * 16];
#pragma unroll
                for (int np = 0; np < 2; np++) {
                    const int base = bn + wn * 32 + np * 16;
                    const float vlo0 = acc[mt][2 * np][2 * rr + 0];
                    const float vlo1 = acc[mt][2 * np][2 * rr + 1];
                    const float vhi0 = acc[mt][2 * np + 1][2 * rr + 0];
                    const float vhi1 = acc[mt][2 * np + 1][2 * rr + 1];
                    if (base < 256) {
                        const int h = base >> 4;
                        float a0 = vlo0 + bQv[h * 16 + i];
                        float a1 = vlo1 + bQv[h * 16 + i + 1];
                        float c0 = vhi0 + bQv[h * 16 + i + 8];
                        float c1 = vhi1 + bQv[h * 16 + i + 9];
                        float sn0 = rt[i], sn1 = rt[i + 1];
                        float cs0 = rt[8 + i], cs1 = rt[9 + i];
                        __half* dst = &g_Qh[((size_t)(b * NQK_ + h) * S_ + s) * DQK_];
                        *(__half2*)&dst[i]     = __floats2half2_rn((a0 * cs0 - c0 * sn0) * QSCALE,
                                                                   (a1 * cs1 - c1 * sn1) * QSCALE);
                        *(__half2*)&dst[i + 8] = __floats2half2_rn((c0 * cs0 + a0 * sn0) * QSCALE,
                                                                   (c1 * cs1 + a1 * sn1) * QSCALE);
                    } else if (base < 512) {
                        const int h = (base - 256) >> 4;
                        float a0 = vlo0 + bKv[h * 16 + i];
                        float a1 = vlo1 + bKv[h * 16 + i + 1];
                        float c0 = vhi0 + bKv[h * 16 + i + 8];
                        float c1 = vhi1 + bKv[h * 16 + i + 9];
                        float sn0 = rt[i], sn1 = rt[i + 1];
                        float cs0 = rt[8 + i], cs1 = rt[9 + i];
                        __half* dst = &g_Kh[((size_t)(b * NQK_ + h) * SK_ + s) * DQK_];
                        *(__half2*)&dst[i]     = __floats2half2_rn(a0 * cs0 - c0 * sn0,
                                                                   a1 * cs1 - c1 * sn1);
                        *(__half2*)&dst[i + 8] = __floats2half2_rn(c0 * cs0 + a0 * sn0,
                                                                   c1 * cs1 + a1 * sn1);
                    } else {
                        const int n0 = base - 512;
                        const int h = n0 >> 4;
                        __half* dst = &g_Vh[((size_t)(b * NQK_ + h) * SK_ + s) * DQK_];
                        *(__half2*)&dst[i]     = __floats2half2_rn(vlo0 + bVv[n0 + i],
                                                                   vlo1 + bVv[n0 + i + 1]);
                        *(__half2*)&dst[i + 8] = __floats2half2_rn(vhi0 + bVv[n0 + i + 8],
                                                                   vhi1 + bVv[n0 + i + 9]);
                    }
                }
            }
        }
    }
}

// ---------------------------------------------------------------------------
// 3) Flash attention: fused antithetic pair, single interleaved pass.
//    CTA pp handles qt_a = 31-pp and qt_b = pp over ONE key sweep
//    (jmax_a >= jmax_b always). K/V loads & barriers drop ~26%.
// ---------------------------------------------------------------------------
__global__ __launch_bounds__(128, 4)
void attn_mma()
{
    grid_dep_sync();

    const int bh   = blockIdx.y;
    const int pp   = blockIdx.x;          // 0..15
    const int tid  = threadIdx.x;
    const int warp = tid >> 5, lane = tid & 31;
    const int qta  = 31 - pp, qtb = pp;
    const int q0a  = qta * 64, q0b = qtb * 64;

    __shared__ __half Qs[128 * PAD];      // rows 0-63: tile A, 64-127: tile B
    __shared__ __half K0s[16 * PAD];
    __shared__ __half V0s[16 * PAD];
    __shared__ __half Ks[2][128 * PAD];
    __shared__ __half Vs[2][128 * PAD];

    const __half* Kg  = g_Kh + (size_t)bh * SK_ * DQK_;
    const __half* Vg  = g_Vh + (size_t)bh * SK_ * DQK_;
    const __half* Qga = g_Qh + ((size_t)bh * S_ + q0a) * DQK_;
    const __half* Qgb = g_Qh + ((size_t)bh * S_ + q0b) * DQK_;

    const int ld_row = tid >> 1;
    const int ld_off = (tid & 1) * 8;

    // Q tiles
    *(float4*)&Qs[ld_row * PAD + ld_off] =
        *(const float4*)&Qga[(size_t)ld_row * 16 + ld_off];
    *(float4*)&Qs[(64 + ld_row) * PAD + ld_off] =
        *(const float4*)&Qgb[(size_t)ld_row * 16 + ld_off];

    // group0: prologue K0/V0 (keys 0..15)
    if (tid < 32) {
        int pr = tid >> 1, po = (tid & 1) * 8;
        cp16(smem_u32(&K0s[pr * PAD + po]), Kg + (size_t)pr * 16 + po);
        cp16(smem_u32(&V0s[pr * PAD + po]), Vg + (size_t)pr * 16 + po);
    }
    asm volatile("cp.async.commit_group;");
    // group1: tile 0 (keys 16..143)
    cp16(smem_u32(&Ks[0][ld_row * PAD + ld_off]),        Kg + (size_t)(16 + ld_row) * 16 + ld_off);
    cp16(smem_u32(&Ks[0][(ld_row + 64) * PAD + ld_off]), Kg + (size_t)(80 + ld_row) * 16 + ld_off);
    cp16(smem_u32(&Vs[0][ld_row * PAD + ld_off]),        Vg + (size_t)(16 + ld_row) * 16 + ld_off);
    cp16(smem_u32(&Vs[0][(ld_row + 64) * PAD + ld_off]), Vg + (size_t)(80 + ld_row) * 16 + ld_off);
    asm volatile("cp.async.commit_group;");

    asm volatile("cp.async.wait_group 1;" ::: "memory");
    __syncthreads();

    const int g = lane >> 3, r = lane & 7;
    const int qfrow = warp * 16 + (g & 1) * 8 + r;
    const int qfcol = (g >> 1) * 8;
    const int krow = (g >> 1) * 8 + r;
    const int kcol = (g & 1) * 8;
    const int vrow = (g & 1) * 8 + r;
    const int vcol = (g >> 1) * 8;
    const uint32_t onesb[2] = { 0x3C003C00u, 0x3C003C00u };

    uint32_t qa_a[4], qa_b[4];
    ldm4(qa_a[0], qa_a[1], qa_a[2], qa_a[3], smem_u32(&Qs[qfrow * PAD + qfcol]));
    ldm4(qa_b[0], qa_b[1], qa_b[2], qa_b[3], smem_u32(&Qs[(64 + qfrow) * PAD + qfcol]));

    float m0a = -1e30f, m1a = -1e30f, m0b = -1e30f, m1b = -1e30f;
    float oA[2][4] = {{0.f,0.f,0.f,0.f},{0.f,0.f,0.f,0.f}};
    float oB[2][4] = {{0.f,0.f,0.f,0.f},{0.f,0.f,0.f,0.f}};
    float oLa[4] = {0.f,0.f,0.f,0.f};
    float oLb[4] = {0.f,0.f,0.f,0.f};

    // ---- prologue: 16 keys, unmasked, both query tiles ----
    {
        const uint32_t k0a = smem_u32(&K0s[krow * PAD + kcol]);
        const uint32_t v0a = smem_u32(&V0s[vrow * PAD + vcol]);
        attn_tile16(qa_a, m0a, m1a, oA, oLa, k0a, v0a, onesb);
        attn_tile16(qa_b, m0b, m1b, oB, oLb, k0a, v0a, onesb);
    }

    const int jmax_a = (q0a + 63) >> 7;   // >= jmax_b always
    const int jmax_b = (q0b + 63) >> 7;

    for (int jt = 0; jt <= jmax_a; jt++) {
        const int buf = jt & 1;
        if (jt < jmax_a) {
            const size_t kb = (size_t)(16 + (jt + 1) * 128);
            cp16(smem_u32(&Ks[buf ^ 1][ld_row * PAD + ld_off]),        Kg + (kb + ld_row) * 16 + ld_off);
            cp16(smem_u32(&Ks[buf ^ 1][(ld_row + 64) * PAD + ld_off]), Kg + (kb + ld_row + 64) * 16 + ld_off);
            cp16(smem_u32(&Vs[buf ^ 1][ld_row * PAD + ld_off]),        Vg + (kb + ld_row) * 16 + ld_off);
            cp16(smem_u32(&Vs[buf ^ 1][(ld_row + 64) * PAD + ld_off]), Vg + (kb + ld_row + 64) * 16 + ld_off);
            asm volatile("cp.async.commit_group;");
            asm volatile("cp.async.wait_group 1;" ::: "memory");
        } else {
            asm volatile("cp.async.wait_group 0;" ::: "memory");
        }
        __syncthreads();

        const uint32_t kaddr = smem_u32(&Ks[buf][krow * PAD + kcol]);
        const uint32_t vaddr = smem_u32(&Vs[buf][vrow * PAD + vcol]);

        // tile for query tile A
        if (jt < jmax_a)
            attn_full_tile(qa_a, m0a, m1a, oA, oLa, kaddr, vaddr, onesb);
        else
            attn_diag_tile(qa_a, m0a, m1a, oA, oLa, kaddr, vaddr, onesb,
                           q0a - 128 * jt, warp, lane);

        // tile for query tile B (only while in range)
        if (jt < jmax_b)
            attn_full_tile(qa_b, m0b, m1b, oB, oLb, kaddr, vaddr, onesb);
        else if (jt == jmax_b)
            attn_diag_tile(qa_b, m0b, m1b, oB, oLb, kaddr, vaddr, onesb,
                           q0b - 128 * jt, warp, lane);

        __syncthreads();
    }

    attn_epilogue(q0a, bh, warp, lane, oA, oLa);
    attn_epilogue(q0b, bh, warp, lane, oB, oLb);
}

// ---------------------------------------------------------------------------
// Launch (PDL chain, unchanged R16)
// ---------------------------------------------------------------------------
template<typename F, typename... Args>
static void launch_pdl(F func, dim3 grid, dim3 block, size_t smem, Args... args)
{
    cudaLaunchConfig_t cfg = {};
    cfg.gridDim = grid;
    cfg.blockDim = block;
    cfg.dynamicSmemBytes = smem;
    cfg.stream = 0;
    cudaLaunchAttribute attr[1];
    attr[0].id = cudaLaunchAttributeProgrammaticStreamSerialization;
    attr[0].val.programmaticStreamSerializationAllowed = 1;
    cfg.attrs = attr;
    cfg.numAttrs = 1;
    cudaLaunchKernelEx(&cfg, func, args...);
}

extern "C" void kernel_launch(void* const* d_in, const int* in_sizes, int n_in,
                              void* d_out, int out_size)
{
    const float* resid = (const float*)d_in[0];
    const float* W_Q   = (const float*)d_in[1];
    const float* W_K   = (const float*)d_in[2];
    const float* W_V   = (const float*)d_in[3];
    const float* W_O   = (const float*)d_in[4];
    const float* b_Q   = (const float*)d_in[5];
    const float* b_K   = (const float*)d_in[6];
    const float* b_V   = (const float*)d_in[7];
    const float* b_O   = (const float*)d_in[8];
    const float* v_k   = (const float*)d_in[9];
    const float* v_v   = (const float*)d_in[10];
    float* out = (float*)d_out;

    __half *Ah, *Wh1, *Wh2, *Zh;
    cudaGetSymbolAddress((void**)&Ah,  g_Ah);
    cudaGetSymbolAddress((void**)&Wh1, g_Wh1);
    cudaGetSymbolAddress((void**)&Wh2, g_Wh2);
    cudaGetSymbolAddress((void**)&Zh,  g_Zh);

    cudaFuncSetAttribute(hgemm<0>, cudaFuncAttributeMaxDynamicSharedMemorySize, HG_SMEM_BYTES);
    cudaFuncSetAttribute(hgemm<1>, cudaFuncAttributeMaxDynamicSharedMemorySize, HG_SMEM_BYTES);

    // 1a) prep_core (Wh1 + Ah)
    prep_core<<<PC_BLKS, 256>>>(W_Q, W_K, W_V, resid);

    // 1b) prep_rest (Wh2 + rot + virtual KV) — concurrent via PDL
    launch_pdl(prep_rest, dim3(PR_BLKS), dim3(256), (size_t)0, W_O, v_k, v_v);

    // 2) GEMM1 + fused bias/rotary/scatter epilogue
    launch_pdl(hgemm<1>, dim3(DM_ / 128, BS_ / 64), dim3(256), (size_t)HG_SMEM_BYTES,
               (const __half*)Ah, (const __half*)Wh1, (float*)nullptr, BS_, DM_, DM_,
               (const float*)nullptr, b_Q, b_K, b_V);

    // 3) fused-pair flash attention
    launch_pdl(attn_mma, dim3(16, B_ * NQK_), dim3(128), (size_t)0);

    // 4) GEMM2
    launch_pdl(hgemm<0>, dim3(DM_ / 128, BS_ / 64), dim3(256), (size_t)HG_SMEM_BYTES,
               (const __half*)Zh, (const __half*)Wh2, out, BS_, DM_, NOV_,
               b_O, (const float*)nullptr, (const float*)nullptr, (const float*)nullptr);
}